// round 16
// baseline (speedup 1.0000x reference)
#include <cuda_runtime.h>
#include <cuda_bf16.h>
#include <math.h>

// Problem constants
#define Bq   4
#define Nq   1024
#define Cq   512
#define Hq   8
#define HDq  64
#define BHq  32
#define Mq   4096
#define SCALEq 0.125f
#define LN_EPSq 1e-5f

// bf16 mma.sync (baseline PTX, compiles under compute_103, runs on HMMA)
__device__ __forceinline__ void mma_bf16(float* d, const unsigned* a,
                                         const unsigned* b) {
    asm volatile(
        "mma.sync.aligned.m16n8k16.row.col.f32.bf16.bf16.f32 "
        "{%0,%1,%2,%3}, {%4,%5,%6,%7}, {%8,%9}, {%0,%1,%2,%3};"
        : "+f"(d[0]), "+f"(d[1]), "+f"(d[2]), "+f"(d[3])
        : "r"(a[0]), "r"(a[1]), "r"(a[2]), "r"(a[3]), "r"(b[0]), "r"(b[1]));
}
__device__ __forceinline__ unsigned pack_bf16x2(float a, float b) {
    unsigned short ha = __bfloat16_as_ushort(__float2bfloat16(a));
    unsigned short hb = __bfloat16_as_ushort(__float2bfloat16(b));
    return (unsigned)ha | ((unsigned)hb << 16);
}

// Scratch (device globals — allocation-free)
__device__ float g_q   [BHq * Nq * HDq];     // [bh][n][d]
__device__ float g_k   [BHq * Nq * HDq];
__device__ float g_vt  [BHq * HDq * Nq];     // [bh][d][n]  (transposed V)
__device__ float g_aoP [2 * Mq * Cq];        // 2 k-split partials of attn-out
__device__ float g_ypP [2 * Mq * Cq];        // 2 k-split partials of proj-out
__device__ float g_pmax[BHq * Nq * 16];      // per-(row, 64col tile) max
__device__ float g_psum[BHq * Nq * 16];      // per-(row, 64col tile) sum exp

#define SST 72   // bf16 elements per smem row (144 B, conflict-free frags)

// ---------------------------------------------------------------------------
// Kernel 1: QKV GEMM via tensor cores (mma.sync bf16x3).
// x[4096,512] @ Wqkv[512,1536] + bqkv -> scatter q/k/vt.
// ---------------------------------------------------------------------------
__global__ __launch_bounds__(256) void k_qkv(const float* __restrict__ A,
                                             const float* __restrict__ Bm,
                                             const float* __restrict__ bias) {
    extern __shared__ char smc[];
    unsigned short* Ah = (unsigned short*)smc;      // [128][SST]
    unsigned short* Al = Ah + 128 * SST;
    unsigned short* Bh = Al + 128 * SST;            // [128][SST] (n-major)
    unsigned short* Bl = Bh + 128 * SST;

    const int K = 512, Nn = 1536;
    int bx = blockIdx.x, by = blockIdx.y;
    int tid = threadIdx.x;
    int w = tid >> 5, lane = tid & 31;
    int wm = (w >> 1) * 32;
    int wn = (w & 1) * 64;
    int lr = lane >> 2;
    int lc = (lane & 3) << 1;

    float d[2][8][4];
#pragma unroll
    for (int mt = 0; mt < 2; mt++)
#pragma unroll
        for (int nt = 0; nt < 8; nt++)
#pragma unroll
            for (int j = 0; j < 4; j++) d[mt][nt][j] = 0.f;

    for (int ch = 0; ch < 8; ch++) {
#pragma unroll
        for (int i = 0; i < 16; i++) {
            int p = tid + i * 256;
            int row = p >> 5;
            int col = (p & 31) << 1;
            float2 av = *(const float2*)(A + (size_t)(by * 128 + row) * K + ch * 64 + col);
            float ahx = __bfloat162float(__float2bfloat16(av.x));
            float ahy = __bfloat162float(__float2bfloat16(av.y));
            int off = row * SST + col;
            *(unsigned*)(Ah + off) = pack_bf16x2(ahx, ahy);
            *(unsigned*)(Al + off) = pack_bf16x2(av.x - ahx, av.y - ahy);
        }
#pragma unroll
        for (int i = 0; i < 16; i++) {
            int p = tid + i * 256;
            int kk = p >> 6;
            int nn = (p & 63) << 1;
            float2 bv = *(const float2*)(Bm + (size_t)(ch * 64 + kk) * Nn + bx * 128 + nn);
            float bhx = __bfloat162float(__float2bfloat16(bv.x));
            float bhy = __bfloat162float(__float2bfloat16(bv.y));
            Bh[nn * SST + kk]       = __bfloat16_as_ushort(__float2bfloat16(bhx));
            Bh[(nn + 1) * SST + kk] = __bfloat16_as_ushort(__float2bfloat16(bhy));
            Bl[nn * SST + kk]       = __bfloat16_as_ushort(__float2bfloat16(bv.x - bhx));
            Bl[(nn + 1) * SST + kk] = __bfloat16_as_ushort(__float2bfloat16(bv.y - bhy));
        }
        __syncthreads();

#pragma unroll
        for (int k0 = 0; k0 < 64; k0 += 16) {
            unsigned ah[2][4], al[2][4], bb[8][2];
#pragma unroll
            for (int mt = 0; mt < 2; mt++) {
                int r0 = (wm + mt * 16 + lr) * SST + k0 + lc;
                int r1 = (wm + mt * 16 + lr + 8) * SST + k0 + lc;
                ah[mt][0] = *(const unsigned*)(Ah + r0);
                ah[mt][1] = *(const unsigned*)(Ah + r1);
                ah[mt][2] = *(const unsigned*)(Ah + r0 + 8);
                ah[mt][3] = *(const unsigned*)(Ah + r1 + 8);
                al[mt][0] = *(const unsigned*)(Al + r0);
                al[mt][1] = *(const unsigned*)(Al + r1);
                al[mt][2] = *(const unsigned*)(Al + r0 + 8);
                al[mt][3] = *(const unsigned*)(Al + r1 + 8);
            }
#pragma unroll
            for (int nt = 0; nt < 8; nt++) {
                int rn = (wn + nt * 8 + lr) * SST + k0 + lc;
                bb[nt][0] = *(const unsigned*)(Bh + rn);
                bb[nt][1] = *(const unsigned*)(Bh + rn + 8);
            }
#pragma unroll
            for (int mt = 0; mt < 2; mt++)
#pragma unroll
                for (int nt = 0; nt < 8; nt++) mma_bf16(d[mt][nt], ah[mt], bb[nt]);
#pragma unroll
            for (int mt = 0; mt < 2; mt++)
#pragma unroll
                for (int nt = 0; nt < 8; nt++) mma_bf16(d[mt][nt], al[mt], bb[nt]);
#pragma unroll
            for (int nt = 0; nt < 8; nt++) {
                int rn = (wn + nt * 8 + lr) * SST + k0 + lc;
                bb[nt][0] = *(const unsigned*)(Bl + rn);
                bb[nt][1] = *(const unsigned*)(Bl + rn + 8);
            }
#pragma unroll
            for (int mt = 0; mt < 2; mt++)
#pragma unroll
                for (int nt = 0; nt < 8; nt++) mma_bf16(d[mt][nt], ah[mt], bb[nt]);
        }
        __syncthreads();
    }

#pragma unroll
    for (int mt = 0; mt < 2; mt++) {
#pragma unroll
        for (int rr = 0; rr < 2; rr++) {
            int r = by * 128 + wm + mt * 16 + lr + rr * 8;
            int bb2 = r >> 10, n = r & 1023;
#pragma unroll
            for (int nt = 0; nt < 8; nt++) {
#pragma unroll
                for (int cc = 0; cc < 2; cc++) {
                    int c = bx * 128 + wn + nt * 8 + lc + cc;
                    float v = d[mt][nt][rr * 2 + cc] + bias[c];
                    int sel = c >> 9;
                    int rem = c & 511;
                    int h = rem >> 6, dd = rem & 63;
                    int bh = bb2 * 8 + h;
                    if (sel == 0)      g_q [((size_t)bh * 1024 + n) * 64 + dd] = v;
                    else if (sel == 1) g_k [((size_t)bh * 1024 + n) * 64 + dd] = v;
                    else               g_vt[((size_t)bh * 64 + dd) * 1024 + n] = v;
                }
            }
        }
    }
}

// ---------------------------------------------------------------------------
// Kernel 2: scores via tensor cores (mma.sync bf16x3) + softmax PARTIALS.
// Writes pre-softmax poly scores to attn, plus per-(row, 64col-tile)
// (max, sum exp) partials for the fused softmax in k_av.
// ---------------------------------------------------------------------------
__global__ __launch_bounds__(256) void k_scores(const float* __restrict__ ow_in,
                                                float* __restrict__ attn) {
    extern __shared__ char smc[];
    unsigned short* Qh = (unsigned short*)smc;
    unsigned short* Ql = Qh + 128 * SST;
    unsigned short* Kh = Ql + 128 * SST;
    unsigned short* Kl = Kh + 128 * SST;

    int bh = blockIdx.z;
    int mb = blockIdx.y * 128;
    int nb = blockIdx.x * 128;
    int tid = threadIdx.x;

    const float* qbase = g_q + (size_t)(bh * 1024 + mb) * 64;
    const float* kbase = g_k + (size_t)(bh * 1024 + nb) * 64;
#pragma unroll
    for (int i = 0; i < 16; i++) {
        int p = tid + i * 256;
        int row = p >> 5;
        int col = (p & 31) << 1;
        float2 qv = *(const float2*)(qbase + row * 64 + col);
        float2 kv = *(const float2*)(kbase + row * 64 + col);
        float qhx = __bfloat162float(__float2bfloat16(qv.x));
        float qhy = __bfloat162float(__float2bfloat16(qv.y));
        float khx = __bfloat162float(__float2bfloat16(kv.x));
        float khy = __bfloat162float(__float2bfloat16(kv.y));
        int off = row * SST + col;
        *(unsigned*)(Qh + off) = pack_bf16x2(qhx, qhy);
        *(unsigned*)(Ql + off) = pack_bf16x2(qv.x - qhx, qv.y - qhy);
        *(unsigned*)(Kh + off) = pack_bf16x2(khx, khy);
        *(unsigned*)(Kl + off) = pack_bf16x2(kv.x - khx, kv.y - khy);
    }
    __syncthreads();

    int w = tid >> 5, lane = tid & 31;
    int wm = (w >> 1) * 32;
    int wn = (w & 1) * 64;
    int lr = lane >> 2;
    int lc = (lane & 3) << 1;

    float d[2][8][4];
#pragma unroll
    for (int mt = 0; mt < 2; mt++)
#pragma unroll
        for (int nt = 0; nt < 8; nt++)
#pragma unroll
            for (int j = 0; j < 4; j++) d[mt][nt][j] = 0.f;

#pragma unroll
    for (int k0 = 0; k0 < 64; k0 += 16) {
        unsigned ah[2][4], al[2][4], bb[8][2];
#pragma unroll
        for (int mt = 0; mt < 2; mt++) {
            int r0 = (wm + mt * 16 + lr) * SST + k0 + lc;
            int r1 = (wm + mt * 16 + lr + 8) * SST + k0 + lc;
            ah[mt][0] = *(const unsigned*)(Qh + r0);
            ah[mt][1] = *(const unsigned*)(Qh + r1);
            ah[mt][2] = *(const unsigned*)(Qh + r0 + 8);
            ah[mt][3] = *(const unsigned*)(Qh + r1 + 8);
            al[mt][0] = *(const unsigned*)(Ql + r0);
            al[mt][1] = *(const unsigned*)(Ql + r1);
            al[mt][2] = *(const unsigned*)(Ql + r0 + 8);
            al[mt][3] = *(const unsigned*)(Ql + r1 + 8);
        }
#pragma unroll
        for (int nt = 0; nt < 8; nt++) {
            int rn = (wn + nt * 8 + lr) * SST + k0 + lc;
            bb[nt][0] = *(const unsigned*)(Kh + rn);
            bb[nt][1] = *(const unsigned*)(Kh + rn + 8);
        }
#pragma unroll
        for (int mt = 0; mt < 2; mt++)
#pragma unroll
            for (int nt = 0; nt < 8; nt++) mma_bf16(d[mt][nt], ah[mt], bb[nt]);
#pragma unroll
        for (int mt = 0; mt < 2; mt++)
#pragma unroll
            for (int nt = 0; nt < 8; nt++) mma_bf16(d[mt][nt], al[mt], bb[nt]);
#pragma unroll
        for (int nt = 0; nt < 8; nt++) {
            int rn = (wn + nt * 8 + lr) * SST + k0 + lc;
            bb[nt][0] = *(const unsigned*)(Kl + rn);
            bb[nt][1] = *(const unsigned*)(Kl + rn + 8);
        }
#pragma unroll
        for (int mt = 0; mt < 2; mt++)
#pragma unroll
            for (int nt = 0; nt < 8; nt++) mma_bf16(d[mt][nt], ah[mt], bb[nt]);
    }

    float w0 = ow_in[0], w1 = ow_in[1], w2 = ow_in[2];
    float mw = fmaxf(w0, fmaxf(w1, w2));
    float e0 = __expf(w0 - mw), e1 = __expf(w1 - mw), e2 = __expf(w2 - mw);
    float inv = 1.f / (e0 + e1 + e2);
    w0 = e0 * inv; w1 = e1 * inv; w2 = e2 * inv;

    // poly transform in place, write pre-softmax scores
#pragma unroll
    for (int mt = 0; mt < 2; mt++) {
        int r0 = bh * 1024 + mb + wm + mt * 16 + lr;
#pragma unroll
        for (int nt = 0; nt < 8; nt++) {
            int col = nb + wn + nt * 8 + lc;
#pragma unroll
            for (int j = 0; j < 4; j++) {
                float s = d[mt][nt][j] * SCALEq;
                d[mt][nt][j] = s * (w0 + s * (w1 + s * w2));
            }
            float2 o0 = {d[mt][nt][0], d[mt][nt][1]};
            float2 o1 = {d[mt][nt][2], d[mt][nt][3]};
            *(float2*)(attn + (size_t)r0 * 1024 + col) = o0;
            *(float2*)(attn + (size_t)(r0 + 8) * 1024 + col) = o1;
        }
    }

    // softmax partials: per (row, this warp's 64-col tile)
    int tile = 2 * blockIdx.x + (w & 1);     // 0..15
#pragma unroll
    for (int mt = 0; mt < 2; mt++) {
#pragma unroll
        for (int rr = 0; rr < 2; rr++) {
            float lm = -3.0e38f;
#pragma unroll
            for (int nt = 0; nt < 8; nt++)
                lm = fmaxf(lm, fmaxf(d[mt][nt][rr * 2], d[mt][nt][rr * 2 + 1]));
            lm = fmaxf(lm, __shfl_xor_sync(0xffffffffu, lm, 1));
            lm = fmaxf(lm, __shfl_xor_sync(0xffffffffu, lm, 2));
            float ls = 0.f;
#pragma unroll
            for (int nt = 0; nt < 8; nt++)
                ls += __expf(d[mt][nt][rr * 2] - lm) + __expf(d[mt][nt][rr * 2 + 1] - lm);
            ls += __shfl_xor_sync(0xffffffffu, ls, 1);
            ls += __shfl_xor_sync(0xffffffffu, ls, 2);
            if ((lane & 3) == 0) {
                size_t r = (size_t)(bh * 1024 + mb + wm + mt * 16 + lr + rr * 8);
                g_pmax[r * 16 + tile] = lm;
                g_psum[r * 16 + tile] = ls;
            }
        }
    }
}

// ---------------------------------------------------------------------------
// Kernel 3: AV via tensor cores (mma.sync bf16x3), K-SPLIT 2, FUSED SOFTMAX.
// Prologue builds exact row (M, 1/L) from the 16 scores partials; A-staging
// applies e = exp(s-M)/L, writes FINAL attn in place (disjoint cols per z),
// and feeds e into the bf16 hi/lo split for the HMMA mainloop.
// ---------------------------------------------------------------------------
__global__ __launch_bounds__(256) void k_av(float* __restrict__ attn) {
    extern __shared__ char smc[];
    unsigned short* Ahh = (unsigned short*)smc;          // [128][SST]
    unsigned short* All = Ahh + 128 * SST;
    unsigned short* Bhh = All + 128 * SST;               // [64][SST]
    unsigned short* Bll = Bhh + 64 * SST;
    float* sM  = (float*)(Bll + 64 * SST);               // [128]
    float* sIL = sM + 128;                               // [128]

    int mb = blockIdx.x * 128;
    int bh = blockIdx.y;
    int zc = blockIdx.z * 8;
    int tid = threadIdx.x;
    int w = tid >> 5, lane = tid & 31;
    int wm = w * 16;
    int lr = lane >> 2;
    int lc = (lane & 3) << 1;

    // prologue: exact row max + inverse sum from 16 per-tile partials
    if (tid < 128) {
        size_t r = (size_t)(bh * 1024 + mb + tid);
        const float* pm = g_pmax + r * 16;
        const float* ps = g_psum + r * 16;
        float M = -3.0e38f;
#pragma unroll
        for (int i = 0; i < 16; i += 4) {
            float4 m4 = *(const float4*)(pm + i);
            M = fmaxf(M, fmaxf(fmaxf(m4.x, m4.y), fmaxf(m4.z, m4.w)));
        }
        float L = 0.f;
#pragma unroll
        for (int i = 0; i < 16; i += 4) {
            float4 m4 = *(const float4*)(pm + i);
            float4 s4 = *(const float4*)(ps + i);
            L += s4.x * __expf(m4.x - M) + s4.y * __expf(m4.y - M)
               + s4.z * __expf(m4.z - M) + s4.w * __expf(m4.w - M);
        }
        sM[tid] = M;
        sIL[tid] = 1.f / L;
    }
    __syncthreads();

    float d[8][4];
#pragma unroll
    for (int nt = 0; nt < 8; nt++)
#pragma unroll
        for (int j = 0; j < 4; j++) d[nt][j] = 0.f;

    float* abase = attn + (size_t)(bh * 1024 + mb) * 1024;
    const float* bbase = g_vt + (size_t)bh * 64 * 1024;

    for (int c8 = 0; c8 < 8; c8++) {
        int ch = zc + c8;
#pragma unroll
        for (int i = 0; i < 16; i++) {
            int p = tid + i * 256;
            int row = p >> 5;
            int col = (p & 31) << 1;
            float* ap = abase + (size_t)row * 1024 + ch * 64 + col;
            float2 av = *(const float2*)ap;
            float M = sM[row], il = sIL[row];
            av.x = __expf(av.x - M) * il;
            av.y = __expf(av.y - M) * il;
            *(float2*)ap = av;              // final attn output (in place)
            float ahx = __bfloat162float(__float2bfloat16(av.x));
            float ahy = __bfloat162float(__float2bfloat16(av.y));
            int off = row * SST + col;
            *(unsigned*)(Ahh + off) = pack_bf16x2(ahx, ahy);
            *(unsigned*)(All + off) = pack_bf16x2(av.x - ahx, av.y - ahy);
        }
#pragma unroll
        for (int i = 0; i < 8; i++) {
            int p = tid + i * 256;
            int row = p >> 5;
            int col = (p & 31) << 1;
            float2 bv = *(const float2*)(bbase + (size_t)row * 1024 + ch * 64 + col);
            float bhx = __bfloat162float(__float2bfloat16(bv.x));
            float bhy = __bfloat162float(__float2bfloat16(bv.y));
            int off = row * SST + col;
            *(unsigned*)(Bhh + off) = pack_bf16x2(bhx, bhy);
            *(unsigned*)(Bll + off) = pack_bf16x2(bv.x - bhx, bv.y - bhy);
        }
        __syncthreads();

#pragma unroll
        for (int k0 = 0; k0 < 64; k0 += 16) {
            unsigned ah[4], al[4], bb[8][2];
            int r0 = (wm + lr) * SST + k0 + lc;
            int r1 = (wm + lr + 8) * SST + k0 + lc;
            ah[0] = *(const unsigned*)(Ahh + r0);
            ah[1] = *(const unsigned*)(Ahh + r1);
            ah[2] = *(const unsigned*)(Ahh + r0 + 8);
            ah[3] = *(const unsigned*)(Ahh + r1 + 8);
            al[0] = *(const unsigned*)(All + r0);
            al[1] = *(const unsigned*)(All + r1);
            al[2] = *(const unsigned*)(All + r0 + 8);
            al[3] = *(const unsigned*)(All + r1 + 8);
#pragma unroll
            for (int nt = 0; nt < 8; nt++) {
                int rn = (nt * 8 + lr) * SST + k0 + lc;
                bb[nt][0] = *(const unsigned*)(Bhh + rn);
                bb[nt][1] = *(const unsigned*)(Bhh + rn + 8);
            }
#pragma unroll
            for (int nt = 0; nt < 8; nt++) mma_bf16(d[nt], ah, bb[nt]);
#pragma unroll
            for (int nt = 0; nt < 8; nt++) mma_bf16(d[nt], al, bb[nt]);
#pragma unroll
            for (int nt = 0; nt < 8; nt++) {
                int rn = (nt * 8 + lr) * SST + k0 + lc;
                bb[nt][0] = *(const unsigned*)(Bll + rn);
                bb[nt][1] = *(const unsigned*)(Bll + rn + 8);
            }
#pragma unroll
            for (int nt = 0; nt < 8; nt++) mma_bf16(d[nt], ah, bb[nt]);
        }
        __syncthreads();
    }

    int b = bh >> 3, h = bh & 7;
    int n0 = mb + wm + lr;
    float* base = g_aoP + (size_t)blockIdx.z * (Mq * Cq);
#pragma unroll
    for (int nt = 0; nt < 8; nt++) {
        int col = h * 64 + nt * 8 + lc;
        float2 o0 = {d[nt][0], d[nt][1]};
        float2 o1 = {d[nt][2], d[nt][3]};
        *(float2*)(base + (size_t)(b * 1024 + n0) * 512 + col) = o0;
        *(float2*)(base + (size_t)(b * 1024 + n0 + 8) * 512 + col) = o1;
    }
}

// ---------------------------------------------------------------------------
// Kernel 4: proj GEMM via tensor cores (mma.sync bf16x3), K-SPLIT 2.
// ---------------------------------------------------------------------------
__global__ __launch_bounds__(256) void k_proj(const float* __restrict__ Bm) {
    extern __shared__ char smc[];
    unsigned short* Ah = (unsigned short*)smc;      // [128][SST]
    unsigned short* Al = Ah + 128 * SST;
    unsigned short* Bh = Al + 128 * SST;            // [128][SST] (n-major)
    unsigned short* Bl = Bh + 128 * SST;

    const int Nn = 512;
    const int P = Mq * Cq;
    int bx = blockIdx.x, by = blockIdx.y, bz = blockIdx.z;
    int tid = threadIdx.x;
    int w = tid >> 5, lane = tid & 31;
    int wm = (w >> 1) * 32;
    int wn = (w & 1) * 64;
    int lr = lane >> 2;
    int lc = (lane & 3) << 1;

    float d[2][8][4];
#pragma unroll
    for (int mt = 0; mt < 2; mt++)
#pragma unroll
        for (int nt = 0; nt < 8; nt++)
#pragma unroll
            for (int j = 0; j < 4; j++) d[mt][nt][j] = 0.f;

    for (int c4 = 0; c4 < 4; c4++) {
        int ch = bz * 4 + c4;
#pragma unroll
        for (int i = 0; i < 16; i++) {
            int p = tid + i * 256;
            int row = p >> 5;
            int col = (p & 31) << 1;
            const float* ap = g_aoP + (size_t)(by * 128 + row) * 512 + ch * 64 + col;
            float2 a0 = *(const float2*)(ap);
            float2 a1 = *(const float2*)(ap + P);
            float vx = a0.x + a1.x;
            float vy = a0.y + a1.y;
            float ahx = __bfloat162float(__float2bfloat16(vx));
            float ahy = __bfloat162float(__float2bfloat16(vy));
            int off = row * SST + col;
            *(unsigned*)(Ah + off) = pack_bf16x2(ahx, ahy);
            *(unsigned*)(Al + off) = pack_bf16x2(vx - ahx, vy - ahy);
        }
#pragma unroll
        for (int i = 0; i < 16; i++) {
            int p = tid + i * 256;
            int kk = p >> 6;
            int nn = (p & 63) << 1;
            float2 bv = *(const float2*)(Bm + (size_t)(ch * 64 + kk) * Nn + bx * 128 + nn);
            float bhx = __bfloat162float(__float2bfloat16(bv.x));
            float bhy = __bfloat162float(__float2bfloat16(bv.y));
            Bh[nn * SST + kk]       = __bfloat16_as_ushort(__float2bfloat16(bhx));
            Bh[(nn + 1) * SST + kk] = __bfloat16_as_ushort(__float2bfloat16(bhy));
            Bl[nn * SST + kk]       = __bfloat16_as_ushort(__float2bfloat16(bv.x - bhx));
            Bl[(nn + 1) * SST + kk] = __bfloat16_as_ushort(__float2bfloat16(bv.y - bhy));
        }
        __syncthreads();

#pragma unroll
        for (int k0 = 0; k0 < 64; k0 += 16) {
            unsigned ah[2][4], al[2][4], bb[8][2];
#pragma unroll
            for (int mt = 0; mt < 2; mt++) {
                int r0 = (wm + mt * 16 + lr) * SST + k0 + lc;
                int r1 = (wm + mt * 16 + lr + 8) * SST + k0 + lc;
                ah[mt][0] = *(const unsigned*)(Ah + r0);
                ah[mt][1] = *(const unsigned*)(Ah + r1);
                ah[mt][2] = *(const unsigned*)(Ah + r0 + 8);
                ah[mt][3] = *(const unsigned*)(Ah + r1 + 8);
                al[mt][0] = *(const unsigned*)(Al + r0);
                al[mt][1] = *(const unsigned*)(Al + r1);
                al[mt][2] = *(const unsigned*)(Al + r0 + 8);
                al[mt][3] = *(const unsigned*)(Al + r1 + 8);
            }
#pragma unroll
            for (int nt = 0; nt < 8; nt++) {
                int rn = (wn + nt * 8 + lr) * SST + k0 + lc;
                bb[nt][0] = *(const unsigned*)(Bh + rn);
                bb[nt][1] = *(const unsigned*)(Bh + rn + 8);
            }
#pragma unroll
            for (int mt = 0; mt < 2; mt++)
#pragma unroll
                for (int nt = 0; nt < 8; nt++) mma_bf16(d[mt][nt], ah[mt], bb[nt]);
#pragma unroll
            for (int mt = 0; mt < 2; mt++)
#pragma unroll
                for (int nt = 0; nt < 8; nt++) mma_bf16(d[mt][nt], al[mt], bb[nt]);
#pragma unroll
            for (int nt = 0; nt < 8; nt++) {
                int rn = (wn + nt * 8 + lr) * SST + k0 + lc;
                bb[nt][0] = *(const unsigned*)(Bl + rn);
                bb[nt][1] = *(const unsigned*)(Bl + rn + 8);
            }
#pragma unroll
            for (int mt = 0; mt < 2; mt++)
#pragma unroll
                for (int nt = 0; nt < 8; nt++) mma_bf16(d[mt][nt], ah[mt], bb[nt]);
        }
        __syncthreads();
    }

    float* yp = g_ypP + (size_t)bz * P;
#pragma unroll
    for (int mt = 0; mt < 2; mt++) {
#pragma unroll
        for (int rr = 0; rr < 2; rr++) {
            int r = by * 128 + wm + mt * 16 + lr + rr * 8;
#pragma unroll
            for (int nt = 0; nt < 8; nt++) {
                int c = bx * 128 + wn + nt * 8 + lc;
                float2 o = {d[mt][nt][rr * 2], d[mt][nt][rr * 2 + 1]};
                *(float2*)(yp + (size_t)r * 512 + c) = o;
            }
        }
    }
}

// ---------------------------------------------------------------------------
// Kernel 5: LayerNorm. y_pre = sum of 2 proj partials + bias + x, then LN.
// ---------------------------------------------------------------------------
__global__ __launch_bounds__(128) void k_ln(const float* __restrict__ gamma,
                                            const float* __restrict__ beta,
                                            const float* __restrict__ bias,
                                            const float* __restrict__ x,
                                            float* __restrict__ y) {
    const int P = Mq * Cq;
    __shared__ float s1[4], s2[4];
    int row = blockIdx.x;
    int tid = threadIdx.x;
    int c = tid * 4;
    const float* p = g_ypP + (size_t)row * 512 + c;
    float4 v0 = *(const float4*)(p);
    float4 v1 = *(const float4*)(p + P);
    float4 bb = *(const float4*)(bias + c);
    float4 xx = *(const float4*)(x + (size_t)row * 512 + c);
    float4 v;
    v.x = v0.x + v1.x + bb.x + xx.x;
    v.y = v0.y + v1.y + bb.y + xx.y;
    v.z = v0.z + v1.z + bb.z + xx.z;
    v.w = v0.w + v1.w + bb.w + xx.w;

    float s = v.x + v.y + v.z + v.w;
    float ss = v.x * v.x + v.y * v.y + v.z * v.z + v.w * v.w;
#pragma unroll
    for (int o = 16; o; o >>= 1) {
        s += __shfl_xor_sync(0xffffffffu, s, o);
        ss += __shfl_xor_sync(0xffffffffu, ss, o);
    }
    int wid = tid >> 5, lane = tid & 31;
    if (lane == 0) { s1[wid] = s; s2[wid] = ss; }
    __syncthreads();
    if (tid == 0) {
        s1[0] = s1[0] + s1[1] + s1[2] + s1[3];
        s2[0] = s2[0] + s2[1] + s2[2] + s2[3];
    }
    __syncthreads();
    float mu = s1[0] * (1.f / 512.f);
    float var = s2[0] * (1.f / 512.f) - mu * mu;
    float rstd = rsqrtf(var + LN_EPSq);

    float4 g = *(const float4*)(gamma + c);
    float4 be = *(const float4*)(beta + c);
    float4 o;
    o.x = (v.x - mu) * rstd * g.x + be.x;
    o.y = (v.y - mu) * rstd * g.y + be.y;
    o.z = (v.z - mu) * rstd * g.z + be.z;
    o.w = (v.w - mu) * rstd * g.w + be.w;
    *(float4*)(y + (size_t)row * 512 + c) = o;
}

// ---------------------------------------------------------------------------
extern "C" void kernel_launch(void* const* d_in, const int* in_sizes, int n_in,
                              void* d_out, int out_size) {
    (void)in_sizes; (void)n_in; (void)out_size;
    const float* x     = (const float*)d_in[0];
    const float* Wqkv  = (const float*)d_in[1];
    const float* bqkv  = (const float*)d_in[2];
    const float* ow    = (const float*)d_in[3];
    const float* Wproj = (const float*)d_in[4];
    const float* bproj = (const float*)d_in[5];
    const float* gamma = (const float*)d_in[6];
    const float* beta  = (const float*)d_in[7];

    float* out      = (float*)d_out;
    float* y_out    = out;                         // [4,1024,512]
    float* attn_out = out + (size_t)Bq * Nq * Cq;  // [4,8,1024,1024]

    int big_smem = 4 * 128 * SST * 2;                            // 73728 B
    int av_smem  = (2 * 128 * SST + 2 * 64 * SST) * 2 + 256 * 4; // 56320 B
    cudaFuncSetAttribute(k_qkv, cudaFuncAttributeMaxDynamicSharedMemorySize,
                         big_smem);
    cudaFuncSetAttribute(k_scores, cudaFuncAttributeMaxDynamicSharedMemorySize,
                         big_smem);
    cudaFuncSetAttribute(k_av, cudaFuncAttributeMaxDynamicSharedMemorySize,
                         av_smem);
    cudaFuncSetAttribute(k_proj, cudaFuncAttributeMaxDynamicSharedMemorySize,
                         big_smem);

    k_qkv    <<<dim3(12, 32), 256, big_smem>>>(x, Wqkv, bqkv);
    k_scores <<<dim3(8, 8, 32), 256, big_smem>>>(ow, attn_out);
    k_av     <<<dim3(8, 32, 2), 256, av_smem>>>(attn_out);
    k_proj   <<<dim3(4, 32, 2), 256, big_smem>>>(Wproj);
    k_ln     <<<4096, 128>>>(gamma, beta, bproj, x, y_out);
}

// round 17
// speedup vs baseline: 1.2509x; 1.2509x over previous
#include <cuda_runtime.h>
#include <cuda_bf16.h>
#include <math.h>

// Problem constants
#define Bq   4
#define Nq   1024
#define Cq   512
#define Hq   8
#define HDq  64
#define BHq  32
#define Mq   4096
#define SCALEq 0.125f
#define LN_EPSq 1e-5f

// bf16 mma.sync (baseline PTX, compiles under compute_103, runs on HMMA)
__device__ __forceinline__ void mma_bf16(float* d, const unsigned* a,
                                         const unsigned* b) {
    asm volatile(
        "mma.sync.aligned.m16n8k16.row.col.f32.bf16.bf16.f32 "
        "{%0,%1,%2,%3}, {%4,%5,%6,%7}, {%8,%9}, {%0,%1,%2,%3};"
        : "+f"(d[0]), "+f"(d[1]), "+f"(d[2]), "+f"(d[3])
        : "r"(a[0]), "r"(a[1]), "r"(a[2]), "r"(a[3]), "r"(b[0]), "r"(b[1]));
}
__device__ __forceinline__ unsigned pack_bf16x2(float a, float b) {
    unsigned short ha = __bfloat16_as_ushort(__float2bfloat16(a));
    unsigned short hb = __bfloat16_as_ushort(__float2bfloat16(b));
    return (unsigned)ha | ((unsigned)hb << 16);
}

// Scratch (device globals — allocation-free)
__device__ float g_q  [BHq * Nq * HDq];     // [bh][n][d]
__device__ float g_k  [BHq * Nq * HDq];
__device__ float g_vt [BHq * HDq * Nq];     // [bh][d][n]  (transposed V)
__device__ float g_aoP[2 * Mq * Cq];        // 2 k-split partials of attn-out
__device__ float g_ypP[2 * Mq * Cq];        // 2 k-split partials of proj-out

#define SST 72   // bf16 elements per smem row (144 B, conflict-free frags)

// ---------------------------------------------------------------------------
// Kernel 1: QKV GEMM via tensor cores (mma.sync bf16x3).
// x[4096,512] @ Wqkv[512,1536] + bqkv -> scatter q/k/vt.
// __launch_bounds__(256,2): cap regs at 128 -> 2 CTAs/SM to hide staging.
// ---------------------------------------------------------------------------
__global__ __launch_bounds__(256, 2) void k_qkv(const float* __restrict__ A,
                                                const float* __restrict__ Bm,
                                                const float* __restrict__ bias) {
    extern __shared__ char smc[];
    unsigned short* Ah = (unsigned short*)smc;      // [128][SST]
    unsigned short* Al = Ah + 128 * SST;
    unsigned short* Bh = Al + 128 * SST;            // [128][SST] (n-major)
    unsigned short* Bl = Bh + 128 * SST;

    const int K = 512, Nn = 1536;
    int bx = blockIdx.x, by = blockIdx.y;
    int tid = threadIdx.x;
    int w = tid >> 5, lane = tid & 31;
    int wm = (w >> 1) * 32;
    int wn = (w & 1) * 64;
    int lr = lane >> 2;
    int lc = (lane & 3) << 1;

    float d[2][8][4];
#pragma unroll
    for (int mt = 0; mt < 2; mt++)
#pragma unroll
        for (int nt = 0; nt < 8; nt++)
#pragma unroll
            for (int j = 0; j < 4; j++) d[mt][nt][j] = 0.f;

    for (int ch = 0; ch < 8; ch++) {
#pragma unroll
        for (int i = 0; i < 16; i++) {
            int p = tid + i * 256;
            int row = p >> 5;
            int col = (p & 31) << 1;
            float2 av = *(const float2*)(A + (size_t)(by * 128 + row) * K + ch * 64 + col);
            float ahx = __bfloat162float(__float2bfloat16(av.x));
            float ahy = __bfloat162float(__float2bfloat16(av.y));
            int off = row * SST + col;
            *(unsigned*)(Ah + off) = pack_bf16x2(ahx, ahy);
            *(unsigned*)(Al + off) = pack_bf16x2(av.x - ahx, av.y - ahy);
        }
#pragma unroll
        for (int i = 0; i < 16; i++) {
            int p = tid + i * 256;
            int kk = p >> 6;
            int nn = (p & 63) << 1;
            float2 bv = *(const float2*)(Bm + (size_t)(ch * 64 + kk) * Nn + bx * 128 + nn);
            float bhx = __bfloat162float(__float2bfloat16(bv.x));
            float bhy = __bfloat162float(__float2bfloat16(bv.y));
            Bh[nn * SST + kk]       = __bfloat16_as_ushort(__float2bfloat16(bhx));
            Bh[(nn + 1) * SST + kk] = __bfloat16_as_ushort(__float2bfloat16(bhy));
            Bl[nn * SST + kk]       = __bfloat16_as_ushort(__float2bfloat16(bv.x - bhx));
            Bl[(nn + 1) * SST + kk] = __bfloat16_as_ushort(__float2bfloat16(bv.y - bhy));
        }
        __syncthreads();

#pragma unroll
        for (int k0 = 0; k0 < 64; k0 += 16) {
            unsigned ah[2][4], al[2][4], bb[8][2];
#pragma unroll
            for (int mt = 0; mt < 2; mt++) {
                int r0 = (wm + mt * 16 + lr) * SST + k0 + lc;
                int r1 = (wm + mt * 16 + lr + 8) * SST + k0 + lc;
                ah[mt][0] = *(const unsigned*)(Ah + r0);
                ah[mt][1] = *(const unsigned*)(Ah + r1);
                ah[mt][2] = *(const unsigned*)(Ah + r0 + 8);
                ah[mt][3] = *(const unsigned*)(Ah + r1 + 8);
                al[mt][0] = *(const unsigned*)(Al + r0);
                al[mt][1] = *(const unsigned*)(Al + r1);
                al[mt][2] = *(const unsigned*)(Al + r0 + 8);
                al[mt][3] = *(const unsigned*)(Al + r1 + 8);
            }
#pragma unroll
            for (int nt = 0; nt < 8; nt++) {
                int rn = (wn + nt * 8 + lr) * SST + k0 + lc;
                bb[nt][0] = *(const unsigned*)(Bh + rn);
                bb[nt][1] = *(const unsigned*)(Bh + rn + 8);
            }
#pragma unroll
            for (int mt = 0; mt < 2; mt++)
#pragma unroll
                for (int nt = 0; nt < 8; nt++) mma_bf16(d[mt][nt], ah[mt], bb[nt]);
#pragma unroll
            for (int mt = 0; mt < 2; mt++)
#pragma unroll
                for (int nt = 0; nt < 8; nt++) mma_bf16(d[mt][nt], al[mt], bb[nt]);
#pragma unroll
            for (int nt = 0; nt < 8; nt++) {
                int rn = (wn + nt * 8 + lr) * SST + k0 + lc;
                bb[nt][0] = *(const unsigned*)(Bl + rn);
                bb[nt][1] = *(const unsigned*)(Bl + rn + 8);
            }
#pragma unroll
            for (int mt = 0; mt < 2; mt++)
#pragma unroll
                for (int nt = 0; nt < 8; nt++) mma_bf16(d[mt][nt], ah[mt], bb[nt]);
        }
        __syncthreads();
    }

#pragma unroll
    for (int mt = 0; mt < 2; mt++) {
#pragma unroll
        for (int rr = 0; rr < 2; rr++) {
            int r = by * 128 + wm + mt * 16 + lr + rr * 8;
            int bb2 = r >> 10, n = r & 1023;
#pragma unroll
            for (int nt = 0; nt < 8; nt++) {
#pragma unroll
                for (int cc = 0; cc < 2; cc++) {
                    int c = bx * 128 + wn + nt * 8 + lc + cc;
                    float v = d[mt][nt][rr * 2 + cc] + bias[c];
                    int sel = c >> 9;
                    int rem = c & 511;
                    int h = rem >> 6, dd = rem & 63;
                    int bh = bb2 * 8 + h;
                    if (sel == 0)      g_q [((size_t)bh * 1024 + n) * 64 + dd] = v;
                    else if (sel == 1) g_k [((size_t)bh * 1024 + n) * 64 + dd] = v;
                    else               g_vt[((size_t)bh * 64 + dd) * 1024 + n] = v;
                }
            }
        }
    }
}

// ---------------------------------------------------------------------------
// Kernel 2: scores via tensor cores (mma.sync bf16x3 split precision).
// ---------------------------------------------------------------------------
__global__ __launch_bounds__(256, 2) void k_scores(const float* __restrict__ ow_in,
                                                   float* __restrict__ attn) {
    extern __shared__ char smc[];
    unsigned short* Qh = (unsigned short*)smc;
    unsigned short* Ql = Qh + 128 * SST;
    unsigned short* Kh = Ql + 128 * SST;
    unsigned short* Kl = Kh + 128 * SST;

    int bh = blockIdx.z;
    int mb = blockIdx.y * 128;
    int nb = blockIdx.x * 128;
    int tid = threadIdx.x;

    const float* qbase = g_q + (size_t)(bh * 1024 + mb) * 64;
    const float* kbase = g_k + (size_t)(bh * 1024 + nb) * 64;
#pragma unroll
    for (int i = 0; i < 16; i++) {
        int p = tid + i * 256;
        int row = p >> 5;
        int col = (p & 31) << 1;
        float2 qv = *(const float2*)(qbase + row * 64 + col);
        float2 kv = *(const float2*)(kbase + row * 64 + col);
        float qhx = __bfloat162float(__float2bfloat16(qv.x));
        float qhy = __bfloat162float(__float2bfloat16(qv.y));
        float khx = __bfloat162float(__float2bfloat16(kv.x));
        float khy = __bfloat162float(__float2bfloat16(kv.y));
        int off = row * SST + col;
        *(unsigned*)(Qh + off) = pack_bf16x2(qhx, qhy);
        *(unsigned*)(Ql + off) = pack_bf16x2(qv.x - qhx, qv.y - qhy);
        *(unsigned*)(Kh + off) = pack_bf16x2(khx, khy);
        *(unsigned*)(Kl + off) = pack_bf16x2(kv.x - khx, kv.y - khy);
    }
    __syncthreads();

    int w = tid >> 5, lane = tid & 31;
    int wm = (w >> 1) * 32;
    int wn = (w & 1) * 64;
    int lr = lane >> 2;
    int lc = (lane & 3) << 1;

    float d[2][8][4];
#pragma unroll
    for (int mt = 0; mt < 2; mt++)
#pragma unroll
        for (int nt = 0; nt < 8; nt++)
#pragma unroll
            for (int j = 0; j < 4; j++) d[mt][nt][j] = 0.f;

#pragma unroll
    for (int k0 = 0; k0 < 64; k0 += 16) {
        unsigned ah[2][4], al[2][4], bb[8][2];
#pragma unroll
        for (int mt = 0; mt < 2; mt++) {
            int r0 = (wm + mt * 16 + lr) * SST + k0 + lc;
            int r1 = (wm + mt * 16 + lr + 8) * SST + k0 + lc;
            ah[mt][0] = *(const unsigned*)(Qh + r0);
            ah[mt][1] = *(const unsigned*)(Qh + r1);
            ah[mt][2] = *(const unsigned*)(Qh + r0 + 8);
            ah[mt][3] = *(const unsigned*)(Qh + r1 + 8);
            al[mt][0] = *(const unsigned*)(Ql + r0);
            al[mt][1] = *(const unsigned*)(Ql + r1);
            al[mt][2] = *(const unsigned*)(Ql + r0 + 8);
            al[mt][3] = *(const unsigned*)(Ql + r1 + 8);
        }
#pragma unroll
        for (int nt = 0; nt < 8; nt++) {
            int rn = (wn + nt * 8 + lr) * SST + k0 + lc;
            bb[nt][0] = *(const unsigned*)(Kh + rn);
            bb[nt][1] = *(const unsigned*)(Kh + rn + 8);
        }
#pragma unroll
        for (int mt = 0; mt < 2; mt++)
#pragma unroll
            for (int nt = 0; nt < 8; nt++) mma_bf16(d[mt][nt], ah[mt], bb[nt]);
#pragma unroll
        for (int mt = 0; mt < 2; mt++)
#pragma unroll
            for (int nt = 0; nt < 8; nt++) mma_bf16(d[mt][nt], al[mt], bb[nt]);
#pragma unroll
        for (int nt = 0; nt < 8; nt++) {
            int rn = (wn + nt * 8 + lr) * SST + k0 + lc;
            bb[nt][0] = *(const unsigned*)(Kl + rn);
            bb[nt][1] = *(const unsigned*)(Kl + rn + 8);
        }
#pragma unroll
        for (int mt = 0; mt < 2; mt++)
#pragma unroll
            for (int nt = 0; nt < 8; nt++) mma_bf16(d[mt][nt], ah[mt], bb[nt]);
    }

    float w0 = ow_in[0], w1 = ow_in[1], w2 = ow_in[2];
    float mw = fmaxf(w0, fmaxf(w1, w2));
    float e0 = __expf(w0 - mw), e1 = __expf(w1 - mw), e2 = __expf(w2 - mw);
    float inv = 1.f / (e0 + e1 + e2);
    w0 = e0 * inv; w1 = e1 * inv; w2 = e2 * inv;

#pragma unroll
    for (int mt = 0; mt < 2; mt++) {
        int r0 = bh * 1024 + mb + wm + mt * 16 + lr;
#pragma unroll
        for (int nt = 0; nt < 8; nt++) {
            int col = nb + wn + nt * 8 + lc;
            float s, p0, p1;
            s = d[mt][nt][0] * SCALEq; p0 = s * (w0 + s * (w1 + s * w2));
            s = d[mt][nt][1] * SCALEq; p1 = s * (w0 + s * (w1 + s * w2));
            float2 o0 = {p0, p1};
            *(float2*)(attn + (size_t)r0 * 1024 + col) = o0;
            s = d[mt][nt][2] * SCALEq; p0 = s * (w0 + s * (w1 + s * w2));
            s = d[mt][nt][3] * SCALEq; p1 = s * (w0 + s * (w1 + s * w2));
            float2 o1 = {p0, p1};
            *(float2*)(attn + (size_t)(r0 + 8) * 1024 + col) = o1;
        }
    }
}

// ---------------------------------------------------------------------------
// Kernel 3: row softmax in place on attn [32768 rows x 1024].
// ---------------------------------------------------------------------------
__global__ __launch_bounds__(256) void k_softmax(float* __restrict__ attn) {
    __shared__ float red[8];
    int row = blockIdx.x;
    int tid = threadIdx.x;
    float* p = attn + (size_t)row * 1024;
    float4 v = *(const float4*)(p + tid * 4);

    float m = fmaxf(fmaxf(v.x, v.y), fmaxf(v.z, v.w));
#pragma unroll
    for (int o = 16; o; o >>= 1) m = fmaxf(m, __shfl_xor_sync(0xffffffffu, m, o));
    int wid = tid >> 5, lane = tid & 31;
    if (lane == 0) red[wid] = m;
    __syncthreads();
    if (tid == 0) {
        float mm = red[0];
#pragma unroll
        for (int i = 1; i < 8; i++) mm = fmaxf(mm, red[i]);
        red[0] = mm;
    }
    __syncthreads();
    m = red[0];
    __syncthreads();

    float4 e;
    e.x = __expf(v.x - m); e.y = __expf(v.y - m);
    e.z = __expf(v.z - m); e.w = __expf(v.w - m);
    float s = e.x + e.y + e.z + e.w;
#pragma unroll
    for (int o = 16; o; o >>= 1) s += __shfl_xor_sync(0xffffffffu, s, o);
    if (lane == 0) red[wid] = s;
    __syncthreads();
    if (tid == 0) {
        float ss = 0.f;
#pragma unroll
        for (int i = 0; i < 8; i++) ss += red[i];
        red[0] = ss;
    }
    __syncthreads();
    float invs = 1.f / red[0];

    e.x *= invs; e.y *= invs; e.z *= invs; e.w *= invs;
    *(float4*)(p + tid * 4) = e;
}

// ---------------------------------------------------------------------------
// Kernel 4: AV via tensor cores (mma.sync bf16x3), K-SPLIT 2.
// ---------------------------------------------------------------------------
__global__ __launch_bounds__(256) void k_av(const float* __restrict__ attn) {
    extern __shared__ char smc[];
    unsigned short* Ahh = (unsigned short*)smc;          // [128][SST]
    unsigned short* All = Ahh + 128 * SST;
    unsigned short* Bhh = All + 128 * SST;               // [64][SST]
    unsigned short* Bll = Bhh + 64 * SST;

    int mb = blockIdx.x * 128;
    int bh = blockIdx.y;
    int zc = blockIdx.z * 8;
    int tid = threadIdx.x;
    int w = tid >> 5, lane = tid & 31;
    int wm = w * 16;
    int lr = lane >> 2;
    int lc = (lane & 3) << 1;

    float d[8][4];
#pragma unroll
    for (int nt = 0; nt < 8; nt++)
#pragma unroll
        for (int j = 0; j < 4; j++) d[nt][j] = 0.f;

    const float* abase = attn + (size_t)(bh * 1024 + mb) * 1024;
    const float* bbase = g_vt + (size_t)bh * 64 * 1024;

    for (int c8 = 0; c8 < 8; c8++) {
        int ch = zc + c8;
#pragma unroll
        for (int i = 0; i < 16; i++) {
            int p = tid + i * 256;
            int row = p >> 5;
            int col = (p & 31) << 1;
            float2 av = *(const float2*)(abase + (size_t)row * 1024 + ch * 64 + col);
            float ahx = __bfloat162float(__float2bfloat16(av.x));
            float ahy = __bfloat162float(__float2bfloat16(av.y));
            int off = row * SST + col;
            *(unsigned*)(Ahh + off) = pack_bf16x2(ahx, ahy);
            *(unsigned*)(All + off) = pack_bf16x2(av.x - ahx, av.y - ahy);
        }
#pragma unroll
        for (int i = 0; i < 8; i++) {
            int p = tid + i * 256;
            int row = p >> 5;
            int col = (p & 31) << 1;
            float2 bv = *(const float2*)(bbase + (size_t)row * 1024 + ch * 64 + col);
            float bhx = __bfloat162float(__float2bfloat16(bv.x));
            float bhy = __bfloat162float(__float2bfloat16(bv.y));
            int off = row * SST + col;
            *(unsigned*)(Bhh + off) = pack_bf16x2(bhx, bhy);
            *(unsigned*)(Bll + off) = pack_bf16x2(bv.x - bhx, bv.y - bhy);
        }
        __syncthreads();

#pragma unroll
        for (int k0 = 0; k0 < 64; k0 += 16) {
            unsigned ah[4], al[4], bb[8][2];
            int r0 = (wm + lr) * SST + k0 + lc;
            int r1 = (wm + lr + 8) * SST + k0 + lc;
            ah[0] = *(const unsigned*)(Ahh + r0);
            ah[1] = *(const unsigned*)(Ahh + r1);
            ah[2] = *(const unsigned*)(Ahh + r0 + 8);
            ah[3] = *(const unsigned*)(Ahh + r1 + 8);
            al[0] = *(const unsigned*)(All + r0);
            al[1] = *(const unsigned*)(All + r1);
            al[2] = *(const unsigned*)(All + r0 + 8);
            al[3] = *(const unsigned*)(All + r1 + 8);
#pragma unroll
            for (int nt = 0; nt < 8; nt++) {
                int rn = (nt * 8 + lr) * SST + k0 + lc;
                bb[nt][0] = *(const unsigned*)(Bhh + rn);
                bb[nt][1] = *(const unsigned*)(Bhh + rn + 8);
            }
#pragma unroll
            for (int nt = 0; nt < 8; nt++) mma_bf16(d[nt], ah, bb[nt]);
#pragma unroll
            for (int nt = 0; nt < 8; nt++) mma_bf16(d[nt], al, bb[nt]);
#pragma unroll
            for (int nt = 0; nt < 8; nt++) {
                int rn = (nt * 8 + lr) * SST + k0 + lc;
                bb[nt][0] = *(const unsigned*)(Bll + rn);
                bb[nt][1] = *(const unsigned*)(Bll + rn + 8);
            }
#pragma unroll
            for (int nt = 0; nt < 8; nt++) mma_bf16(d[nt], ah, bb[nt]);
        }
        __syncthreads();
    }

    int b = bh >> 3, h = bh & 7;
    int n0 = mb + wm + lr;
    float* base = g_aoP + (size_t)blockIdx.z * (Mq * Cq);
#pragma unroll
    for (int nt = 0; nt < 8; nt++) {
        int col = h * 64 + nt * 8 + lc;
        float2 o0 = {d[nt][0], d[nt][1]};
        float2 o1 = {d[nt][2], d[nt][3]};
        *(float2*)(base + (size_t)(b * 1024 + n0) * 512 + col) = o0;
        *(float2*)(base + (size_t)(b * 1024 + n0 + 8) * 512 + col) = o1;
    }
}

// ---------------------------------------------------------------------------
// Kernel 5: proj GEMM via tensor cores (mma.sync bf16x3), K-SPLIT 2.
// ---------------------------------------------------------------------------
__global__ __launch_bounds__(256, 2) void k_proj(const float* __restrict__ Bm) {
    extern __shared__ char smc[];
    unsigned short* Ah = (unsigned short*)smc;      // [128][SST]
    unsigned short* Al = Ah + 128 * SST;
    unsigned short* Bh = Al + 128 * SST;            // [128][SST] (n-major)
    unsigned short* Bl = Bh + 128 * SST;

    const int Nn = 512;
    const int P = Mq * Cq;
    int bx = blockIdx.x, by = blockIdx.y, bz = blockIdx.z;
    int tid = threadIdx.x;
    int w = tid >> 5, lane = tid & 31;
    int wm = (w >> 1) * 32;
    int wn = (w & 1) * 64;
    int lr = lane >> 2;
    int lc = (lane & 3) << 1;

    float d[2][8][4];
#pragma unroll
    for (int mt = 0; mt < 2; mt++)
#pragma unroll
        for (int nt = 0; nt < 8; nt++)
#pragma unroll
            for (int j = 0; j < 4; j++) d[mt][nt][j] = 0.f;

    for (int c4 = 0; c4 < 4; c4++) {
        int ch = bz * 4 + c4;
#pragma unroll
        for (int i = 0; i < 16; i++) {
            int p = tid + i * 256;
            int row = p >> 5;
            int col = (p & 31) << 1;
            const float* ap = g_aoP + (size_t)(by * 128 + row) * 512 + ch * 64 + col;
            float2 a0 = *(const float2*)(ap);
            float2 a1 = *(const float2*)(ap + P);
            float vx = a0.x + a1.x;
            float vy = a0.y + a1.y;
            float ahx = __bfloat162float(__float2bfloat16(vx));
            float ahy = __bfloat162float(__float2bfloat16(vy));
            int off = row * SST + col;
            *(unsigned*)(Ah + off) = pack_bf16x2(ahx, ahy);
            *(unsigned*)(Al + off) = pack_bf16x2(vx - ahx, vy - ahy);
        }
#pragma unroll
        for (int i = 0; i < 16; i++) {
            int p = tid + i * 256;
            int kk = p >> 6;
            int nn = (p & 63) << 1;
            float2 bv = *(const float2*)(Bm + (size_t)(ch * 64 + kk) * Nn + bx * 128 + nn);
            float bhx = __bfloat162float(__float2bfloat16(bv.x));
            float bhy = __bfloat162float(__float2bfloat16(bv.y));
            Bh[nn * SST + kk]       = __bfloat16_as_ushort(__float2bfloat16(bhx));
            Bh[(nn + 1) * SST + kk] = __bfloat16_as_ushort(__float2bfloat16(bhy));
            Bl[nn * SST + kk]       = __bfloat16_as_ushort(__float2bfloat16(bv.x - bhx));
            Bl[(nn + 1) * SST + kk] = __bfloat16_as_ushort(__float2bfloat16(bv.y - bhy));
        }
        __syncthreads();

#pragma unroll
        for (int k0 = 0; k0 < 64; k0 += 16) {
            unsigned ah[2][4], al[2][4], bb[8][2];
#pragma unroll
            for (int mt = 0; mt < 2; mt++) {
                int r0 = (wm + mt * 16 + lr) * SST + k0 + lc;
                int r1 = (wm + mt * 16 + lr + 8) * SST + k0 + lc;
                ah[mt][0] = *(const unsigned*)(Ah + r0);
                ah[mt][1] = *(const unsigned*)(Ah + r1);
                ah[mt][2] = *(const unsigned*)(Ah + r0 + 8);
                ah[mt][3] = *(const unsigned*)(Ah + r1 + 8);
                al[mt][0] = *(const unsigned*)(Al + r0);
                al[mt][1] = *(const unsigned*)(Al + r1);
                al[mt][2] = *(const unsigned*)(Al + r0 + 8);
                al[mt][3] = *(const unsigned*)(Al + r1 + 8);
            }
#pragma unroll
            for (int nt = 0; nt < 8; nt++) {
                int rn = (wn + nt * 8 + lr) * SST + k0 + lc;
                bb[nt][0] = *(const unsigned*)(Bh + rn);
                bb[nt][1] = *(const unsigned*)(Bh + rn + 8);
            }
#pragma unroll
            for (int mt = 0; mt < 2; mt++)
#pragma unroll
                for (int nt = 0; nt < 8; nt++) mma_bf16(d[mt][nt], ah[mt], bb[nt]);
#pragma unroll
            for (int mt = 0; mt < 2; mt++)
#pragma unroll
                for (int nt = 0; nt < 8; nt++) mma_bf16(d[mt][nt], al[mt], bb[nt]);
#pragma unroll
            for (int nt = 0; nt < 8; nt++) {
                int rn = (wn + nt * 8 + lr) * SST + k0 + lc;
                bb[nt][0] = *(const unsigned*)(Bl + rn);
                bb[nt][1] = *(const unsigned*)(Bl + rn + 8);
            }
#pragma unroll
            for (int mt = 0; mt < 2; mt++)
#pragma unroll
                for (int nt = 0; nt < 8; nt++) mma_bf16(d[mt][nt], ah[mt], bb[nt]);
        }
        __syncthreads();
    }

    float* yp = g_ypP + (size_t)bz * P;
#pragma unroll
    for (int mt = 0; mt < 2; mt++) {
#pragma unroll
        for (int rr = 0; rr < 2; rr++) {
            int r = by * 128 + wm + mt * 16 + lr + rr * 8;
#pragma unroll
            for (int nt = 0; nt < 8; nt++) {
                int c = bx * 128 + wn + nt * 8 + lc;
                float2 o = {d[mt][nt][rr * 2], d[mt][nt][rr * 2 + 1]};
                *(float2*)(yp + (size_t)r * 512 + c) = o;
            }
        }
    }
}

// ---------------------------------------------------------------------------
// Kernel 6: LayerNorm. y_pre = sum of 2 proj partials + bias + x, then LN.
// ---------------------------------------------------------------------------
__global__ __launch_bounds__(128) void k_ln(const float* __restrict__ gamma,
                                            const float* __restrict__ beta,
                                            const float* __restrict__ bias,
                                            const float* __restrict__ x,
                                            float* __restrict__ y) {
    const int P = Mq * Cq;
    __shared__ float s1[4], s2[4];
    int row = blockIdx.x;
    int tid = threadIdx.x;
    int c = tid * 4;
    const float* p = g_ypP + (size_t)row * 512 + c;
    float4 v0 = *(const float4*)(p);
    float4 v1 = *(const float4*)(p + P);
    float4 bb = *(const float4*)(bias + c);
    float4 xx = *(const float4*)(x + (size_t)row * 512 + c);
    float4 v;
    v.x = v0.x + v1.x + bb.x + xx.x;
    v.y = v0.y + v1.y + bb.y + xx.y;
    v.z = v0.z + v1.z + bb.z + xx.z;
    v.w = v0.w + v1.w + bb.w + xx.w;

    float s = v.x + v.y + v.z + v.w;
    float ss = v.x * v.x + v.y * v.y + v.z * v.z + v.w * v.w;
#pragma unroll
    for (int o = 16; o; o >>= 1) {
        s += __shfl_xor_sync(0xffffffffu, s, o);
        ss += __shfl_xor_sync(0xffffffffu, ss, o);
    }
    int wid = tid >> 5, lane = tid & 31;
    if (lane == 0) { s1[wid] = s; s2[wid] = ss; }
    __syncthreads();
    if (tid == 0) {
        s1[0] = s1[0] + s1[1] + s1[2] + s1[3];
        s2[0] = s2[0] + s2[1] + s2[2] + s2[3];
    }
    __syncthreads();
    float mu = s1[0] * (1.f / 512.f);
    float var = s2[0] * (1.f / 512.f) - mu * mu;
    float rstd = rsqrtf(var + LN_EPSq);

    float4 g = *(const float4*)(gamma + c);
    float4 be = *(const float4*)(beta + c);
    float4 o;
    o.x = (v.x - mu) * rstd * g.x + be.x;
    o.y = (v.y - mu) * rstd * g.y + be.y;
    o.z = (v.z - mu) * rstd * g.z + be.z;
    o.w = (v.w - mu) * rstd * g.w + be.w;
    *(float4*)(y + (size_t)row * 512 + c) = o;
}

// ---------------------------------------------------------------------------
extern "C" void kernel_launch(void* const* d_in, const int* in_sizes, int n_in,
                              void* d_out, int out_size) {
    (void)in_sizes; (void)n_in; (void)out_size;
    const float* x     = (const float*)d_in[0];
    const float* Wqkv  = (const float*)d_in[1];
    const float* bqkv  = (const float*)d_in[2];
    const float* ow    = (const float*)d_in[3];
    const float* Wproj = (const float*)d_in[4];
    const float* bproj = (const float*)d_in[5];
    const float* gamma = (const float*)d_in[6];
    const float* beta  = (const float*)d_in[7];

    float* out      = (float*)d_out;
    float* y_out    = out;                         // [4,1024,512]
    float* attn_out = out + (size_t)Bq * Nq * Cq;  // [4,8,1024,1024]

    int big_smem = 4 * 128 * SST * 2;                     // 73728 B
    int av_smem  = (2 * 128 * SST + 2 * 64 * SST) * 2;    // 55296 B
    cudaFuncSetAttribute(k_qkv, cudaFuncAttributeMaxDynamicSharedMemorySize,
                         big_smem);
    cudaFuncSetAttribute(k_scores, cudaFuncAttributeMaxDynamicSharedMemorySize,
                         big_smem);
    cudaFuncSetAttribute(k_av, cudaFuncAttributeMaxDynamicSharedMemorySize,
                         av_smem);
    cudaFuncSetAttribute(k_proj, cudaFuncAttributeMaxDynamicSharedMemorySize,
                         big_smem);

    k_qkv    <<<dim3(12, 32), 256, big_smem>>>(x, Wqkv, bqkv);
    k_scores <<<dim3(8, 8, 32), 256, big_smem>>>(ow, attn_out);
    k_softmax<<<32768, 256>>>(attn_out);
    k_av     <<<dim3(8, 32, 2), 256, av_smem>>>(attn_out);
    k_proj   <<<dim3(4, 32, 2), 256, big_smem>>>(Wproj);
    k_ln     <<<4096, 128>>>(gamma, beta, bproj, x, y_out);
}